// round 2
// baseline (speedup 1.0000x reference)
#include <cuda_runtime.h>
#include <cuda_bf16.h>
#include <math.h>

// Problem constants (fixed by the dataset)
#define N_NODES   100000
#define E_EDGES   1600000
#define HDIM      64
#define OUT_DIM   32
#define NUM_GRAPHS 64

#define SCAN_TILE 1024
#define NB_SCAN   ((N_NODES + SCAN_TILE - 1) / SCAN_TILE)   // 98

// ---------------- scratch (static device globals; no allocation) ------------
__device__ int   g_deg[N_NODES];
__device__ int   g_rowptr[N_NODES + 1];
__device__ int   g_cursor[N_NODES];
__device__ int   g_bsums[NB_SCAN];
__device__ int   g_boffs[NB_SCAN];
__device__ int   g_csr[E_EDGES];
__device__ __align__(16) float g_dinv[N_NODES];
__device__ __align__(16) float g_t [N_NODES * HDIM];
__device__ __align__(16) float g_r [N_NODES * HDIM];
__device__ __align__(16) float g_h1[N_NODES * HDIM];
__device__ __align__(16) float g_h2[N_NODES * HDIM];

// ---------------- tiny helpers ----------------------------------------------
__global__ void zero_deg_kernel() {
    int i = blockIdx.x * blockDim.x + threadIdx.x;
    int stride = gridDim.x * blockDim.x;
    for (; i < N_NODES; i += stride) g_deg[i] = 0;
}

__global__ void count_deg_kernel(const int* __restrict__ col, int E) {
    int i = blockIdx.x * blockDim.x + threadIdx.x;
    int stride = gridDim.x * blockDim.x;
    for (; i < E; i += stride) {
        atomicAdd(&g_deg[col[i]], 1);
    }
}

// ---- 2-level exclusive scan of g_deg -> g_rowptr / g_cursor, plus dinv -----
__global__ void __launch_bounds__(256) scan_a_kernel() {
    int b = blockIdx.x;
    int tid = threadIdx.x;
    int base = b * SCAN_TILE + tid * 4;
    int s = 0;
#pragma unroll
    for (int j = 0; j < 4; j++) {
        int idx = base + j;
        if (idx < N_NODES) s += g_deg[idx];
    }
    for (int o = 16; o > 0; o >>= 1) s += __shfl_down_sync(0xffffffffu, s, o);
    __shared__ int wsum[8];
    int lane = tid & 31, warp = tid >> 5;
    if (lane == 0) wsum[warp] = s;
    __syncthreads();
    if (tid == 0) {
        int t = 0;
        for (int w = 0; w < 8; w++) t += wsum[w];
        g_bsums[b] = t;
    }
}

__global__ void scan_b_kernel() {
    int running = 0;
    for (int b = 0; b < NB_SCAN; b++) {
        g_boffs[b] = running;
        running += g_bsums[b];
    }
    g_rowptr[N_NODES] = running;
}

__global__ void __launch_bounds__(256) scan_c_kernel() {
    int b = blockIdx.x;
    int tid = threadIdx.x;
    int lane = tid & 31, warp = tid >> 5;
    int base = b * SCAN_TILE + tid * 4;
    int d[4];
#pragma unroll
    for (int j = 0; j < 4; j++) {
        int idx = base + j;
        d[j] = (idx < N_NODES) ? g_deg[idx] : 0;
    }
    int tsum = d[0] + d[1] + d[2] + d[3];
    int incl = tsum;
    for (int o = 1; o < 32; o <<= 1) {
        int v = __shfl_up_sync(0xffffffffu, incl, o);
        if (lane >= o) incl += v;
    }
    int excl = incl - tsum;
    __shared__ int wsum[8];
    if (lane == 31) wsum[warp] = incl;
    __syncthreads();
    int woff = 0;
    for (int w = 0; w < warp; w++) woff += wsum[w];
    int off = g_boffs[b] + woff + excl;
#pragma unroll
    for (int j = 0; j < 4; j++) {
        int idx = base + j;
        if (idx < N_NODES) {
            g_rowptr[idx] = off;
            g_cursor[idx] = off;
            g_dinv[idx]   = (d[j] > 0) ? rsqrtf((float)d[j]) : 0.0f;
            off += d[j];
        }
    }
}

__global__ void fill_csr_kernel(const int* __restrict__ row,
                                const int* __restrict__ col, int E) {
    int i = blockIdx.x * blockDim.x + threadIdx.x;
    int stride = gridDim.x * blockDim.x;
    for (; i < E; i += stride) {
        int c = col[i];
        int p = atomicAdd(&g_cursor[c], 1);
        g_csr[p] = row[i];
    }
}

// ---------------- fused dual GEMM: T = dinv .* (X@Wi),  R = X@Wr ------------
// X: [n,64] row-major, Wi/Wr: [64,64] row-major.
// use_ext: X comes from Xext; otherwise X = g_h1 (layer-2 input).
__global__ void __launch_bounds__(256) gemm_dual_kernel(
    const float* __restrict__ Xext, int use_ext,
    const float* __restrict__ Wi, const float* __restrict__ Wr, int n)
{
    const float* X = use_ext ? Xext : (const float*)g_h1;

    __shared__ float  sX [64][64];
    __shared__ float4 sWi[64][16];
    __shared__ float4 sWr[64][16];
    int tid  = threadIdx.x;
    int row0 = blockIdx.x * 64;

    {
        const float4* wi4 = (const float4*)Wi;
        const float4* wr4 = (const float4*)Wr;
        for (int i = tid; i < 1024; i += 256) {
            sWi[i >> 4][i & 15] = wi4[i];
            sWr[i >> 4][i & 15] = wr4[i];
        }
        const float4* x4 = (const float4*)X;
        for (int i = tid; i < 1024; i += 256) {
            int r = i >> 4, c = i & 15;
            float4 v = make_float4(0.f, 0.f, 0.f, 0.f);
            if (row0 + r < n) v = x4[(size_t)(row0 + r) * 16 + c];
            *((float4*)&sX[r][c * 4]) = v;
        }
    }
    __syncthreads();

    int cg = tid & 15;       // column group (float4 index 0..15)
    int rg = tid >> 4;       // row group 0..15
    int r0 = rg * 4;

    float4 ai[4], ar[4];
#pragma unroll
    for (int i = 0; i < 4; i++) {
        ai[i] = make_float4(0.f, 0.f, 0.f, 0.f);
        ar[i] = make_float4(0.f, 0.f, 0.f, 0.f);
    }

#pragma unroll 16
    for (int k = 0; k < 64; k++) {
        float4 bi = sWi[k][cg];
        float4 br = sWr[k][cg];
        float a0 = sX[r0 + 0][k];
        float a1 = sX[r0 + 1][k];
        float a2 = sX[r0 + 2][k];
        float a3 = sX[r0 + 3][k];
        ai[0].x = fmaf(a0, bi.x, ai[0].x); ai[0].y = fmaf(a0, bi.y, ai[0].y);
        ai[0].z = fmaf(a0, bi.z, ai[0].z); ai[0].w = fmaf(a0, bi.w, ai[0].w);
        ai[1].x = fmaf(a1, bi.x, ai[1].x); ai[1].y = fmaf(a1, bi.y, ai[1].y);
        ai[1].z = fmaf(a1, bi.z, ai[1].z); ai[1].w = fmaf(a1, bi.w, ai[1].w);
        ai[2].x = fmaf(a2, bi.x, ai[2].x); ai[2].y = fmaf(a2, bi.y, ai[2].y);
        ai[2].z = fmaf(a2, bi.z, ai[2].z); ai[2].w = fmaf(a2, bi.w, ai[2].w);
        ai[3].x = fmaf(a3, bi.x, ai[3].x); ai[3].y = fmaf(a3, bi.y, ai[3].y);
        ai[3].z = fmaf(a3, bi.z, ai[3].z); ai[3].w = fmaf(a3, bi.w, ai[3].w);

        ar[0].x = fmaf(a0, br.x, ar[0].x); ar[0].y = fmaf(a0, br.y, ar[0].y);
        ar[0].z = fmaf(a0, br.z, ar[0].z); ar[0].w = fmaf(a0, br.w, ar[0].w);
        ar[1].x = fmaf(a1, br.x, ar[1].x); ar[1].y = fmaf(a1, br.y, ar[1].y);
        ar[1].z = fmaf(a1, br.z, ar[1].z); ar[1].w = fmaf(a1, br.w, ar[1].w);
        ar[2].x = fmaf(a2, br.x, ar[2].x); ar[2].y = fmaf(a2, br.y, ar[2].y);
        ar[2].z = fmaf(a2, br.z, ar[2].z); ar[2].w = fmaf(a2, br.w, ar[2].w);
        ar[3].x = fmaf(a3, br.x, ar[3].x); ar[3].y = fmaf(a3, br.y, ar[3].y);
        ar[3].z = fmaf(a3, br.z, ar[3].z); ar[3].w = fmaf(a3, br.w, ar[3].w);
    }

#pragma unroll
    for (int i = 0; i < 4; i++) {
        int r = row0 + r0 + i;
        if (r < n) {
            float dv = g_dinv[r];
            float4 t = make_float4(ai[i].x * dv, ai[i].y * dv, ai[i].z * dv, ai[i].w * dv);
            ((float4*)g_t)[(size_t)r * 16 + cg] = t;
            ((float4*)g_r)[(size_t)r * 16 + cg] = ar[i];
        }
    }
}

// ---------------- propagate + root + bias + relu ----------------------------
// H[dst] = relu( dinv[dst] * sum_{e: col=dst} T[src_e]  + R[dst] + bias )
// layer: 0 -> write g_h1, 1 -> write g_h2
__global__ void __launch_bounds__(256) prop_combine_kernel(
    const float* __restrict__ bias, int layer)
{
    float* H = layer == 0 ? g_h1 : g_h2;

    int warp = (blockIdx.x * blockDim.x + threadIdx.x) >> 5;
    int lane = threadIdx.x & 31;
    if (warp >= N_NODES) return;
    int node = warp;

    int s = g_rowptr[node];
    int e = g_rowptr[node + 1];

    const float2* T2 = (const float2*)g_t;
    float2 acc0 = make_float2(0.f, 0.f);
    float2 acc1 = make_float2(0.f, 0.f);

    int i = s;
    for (; i + 1 < e; i += 2) {
        int s0 = __ldg(&g_csr[i]);
        int s1 = __ldg(&g_csr[i + 1]);
        float2 v0 = T2[(size_t)s0 * 32 + lane];
        float2 v1 = T2[(size_t)s1 * 32 + lane];
        acc0.x += v0.x; acc0.y += v0.y;
        acc1.x += v1.x; acc1.y += v1.y;
    }
    if (i < e) {
        int s0 = __ldg(&g_csr[i]);
        float2 v0 = T2[(size_t)s0 * 32 + lane];
        acc0.x += v0.x; acc0.y += v0.y;
    }
    acc0.x += acc1.x; acc0.y += acc1.y;

    float dv = g_dinv[node];
    float2 r = ((const float2*)g_r)[(size_t)node * 32 + lane];
    float bx = bias[2 * lane], by = bias[2 * lane + 1];
    float hx = fmaf(dv, acc0.x, r.x + bx);
    float hy = fmaf(dv, acc0.y, r.y + by);
    hx = hx > 0.f ? hx : 0.f;
    hy = hy > 0.f ? hy : 0.f;
    ((float2*)H)[(size_t)node * 32 + lane] = make_float2(hx, hy);
}

// ---------------- global mean pool (sorted batch) + final FC ----------------
__device__ __forceinline__ int lbound_i(const int* a, int n, int key) {
    int lo = 0, hi = n;
    while (lo < hi) {
        int mid = (lo + hi) >> 1;
        if (a[mid] < key) lo = mid + 1; else hi = mid;
    }
    return lo;
}

__global__ void __launch_bounds__(256) pool_fc_kernel(
    const int* __restrict__ batch,
    const float* __restrict__ fcw, const float* __restrict__ fcb,
    float* __restrict__ out)
{
    const float* H = g_h2;
    int g = blockIdx.x;
    int tid = threadIdx.x;
    __shared__ int bounds[2];
    if (tid == 0) bounds[0] = lbound_i(batch, N_NODES, g);
    if (tid == 1) bounds[1] = lbound_i(batch, N_NODES, g + 1);
    __syncthreads();
    int lo = bounds[0], hi = bounds[1];

    int f   = tid & 63;     // feature
    int grp = tid >> 6;     // 0..3
    float acc = 0.f;
    for (int nidx = lo + grp; nidx < hi; nidx += 4)
        acc += H[(size_t)nidx * 64 + f];

    __shared__ float part[4][64];
    part[grp][f] = acc;
    __syncthreads();

    __shared__ float pooled[64];
    if (tid < 64) {
        float sfull = part[0][tid] + part[1][tid] + part[2][tid] + part[3][tid];
        int cnt = hi - lo;
        pooled[tid] = sfull / (float)(cnt > 0 ? cnt : 1);
    }
    __syncthreads();

    if (tid < OUT_DIM) {
        float o = fcb[tid];
#pragma unroll 8
        for (int k = 0; k < 64; k++) o = fmaf(pooled[k], fcw[k * OUT_DIM + tid], o);
        out[g * OUT_DIM + tid] = o;
    }
}

// ---------------- launcher ---------------------------------------------------
extern "C" void kernel_launch(void* const* d_in, const int* in_sizes, int n_in,
                              void* d_out, int out_size)
{
    const float* x     = (const float*)d_in[0];
    const int*   ei    = (const int*)d_in[1];     // [2, E] int32 (JAX x64 off)
    const int*   batch = (const int*)d_in[2];
    const float* w1i   = (const float*)d_in[3];
    const float* w1r   = (const float*)d_in[4];
    const float* b1    = (const float*)d_in[5];
    const float* w2i   = (const float*)d_in[6];
    const float* w2r   = (const float*)d_in[7];
    const float* b2    = (const float*)d_in[8];
    const float* fcw   = (const float*)d_in[9];
    const float* fcb   = (const float*)d_in[10];
    float*       out   = (float*)d_out;

    const int E = in_sizes[1] / 2;            // 1600000
    const int* row = ei;
    const int* col = ei + E;

    // 1) degrees
    zero_deg_kernel<<<196, 512>>>();
    count_deg_kernel<<<(E + 511) / 512, 512>>>(col, E);
    // 2) scan -> rowptr, cursor, dinv
    scan_a_kernel<<<NB_SCAN, 256>>>();
    scan_b_kernel<<<1, 1>>>();
    scan_c_kernel<<<NB_SCAN, 256>>>();
    // 3) CSR fill
    fill_csr_kernel<<<(E + 511) / 512, 512>>>(row, col, E);

    const int gemm_blocks = (N_NODES + 63) / 64;
    // 4) layer 1
    gemm_dual_kernel<<<gemm_blocks, 256>>>(x, 1, w1i, w1r, N_NODES);
    prop_combine_kernel<<<(N_NODES * 32 + 255) / 256, 256>>>(b1, 0);
    // 5) layer 2
    gemm_dual_kernel<<<gemm_blocks, 256>>>(nullptr, 0, w2i, w2r, N_NODES);
    prop_combine_kernel<<<(N_NODES * 32 + 255) / 256, 256>>>(b2, 1);
    // 6) pool + fc
    pool_fc_kernel<<<NUM_GRAPHS, 256>>>(batch, fcw, fcb, out);
}

// round 4
// speedup vs baseline: 1.0805x; 1.0805x over previous
#include <cuda_runtime.h>
#include <cuda_bf16.h>
#include <math.h>

// Problem constants (fixed by the dataset)
#define N_NODES   100000
#define E_EDGES   1600000
#define HDIM      64
#define OUT_DIM   32
#define NUM_GRAPHS 64

#define SCAN_TILE 1024
#define NB_SCAN   ((N_NODES + SCAN_TILE - 1) / SCAN_TILE)   // 98

// tensor GEMM geometry (mma.sync path)
#define TILE_M    128
#define KTOT      192            // [Ah|Ah|Al] x [Bh;Bl;Bh]
#define N2        128            // Wi|Wr side by side
#define KSTEPS    (KTOT / 16)    // 12
#define A_STRIDE  200            // bf16 elems per A row (192 + 8 pad)
#define B_STRIDE  136            // bf16 elems per B row (128 + 8 pad)
#define A_BYTES   (TILE_M * A_STRIDE * 2)     // 51200
#define B_BYTES   (KTOT * B_STRIDE * 2)       // 52224
#define GEMM_SMEM (A_BYTES + B_BYTES)         // 103424
#define GEMM_TILES ((N_NODES + TILE_M - 1) / TILE_M)   // 782

// ---------------- scratch (static device globals; no allocation) ------------
__device__ int   g_deg[N_NODES];
__device__ int   g_rowptr[N_NODES + 1];
__device__ int   g_cursor[N_NODES];
__device__ int   g_bsums[NB_SCAN];
__device__ int   g_boffs[NB_SCAN];
__device__ int   g_csr[E_EDGES];
__device__ __align__(16) float g_dinv[N_NODES];
__device__ __align__(16) float g_t [N_NODES * HDIM];
__device__ __align__(16) float g_r [N_NODES * HDIM];
__device__ __align__(16) float g_h1[N_NODES * HDIM];
__device__ __align__(16) float g_h2[N_NODES * HDIM];
__device__ __align__(16) unsigned short g_wb[2][KTOT * B_STRIDE];  // padded B images

// ---------------- PTX helpers ------------------------------------------------
__device__ __forceinline__ unsigned smem_u32(const void* p) {
    unsigned a;
    asm("{ .reg .u64 t; cvta.to.shared.u64 t, %1; cvt.u32.u64 %0, t; }" : "=r"(a) : "l"(p));
    return a;
}
__device__ __forceinline__ void ldsm_x4(unsigned& r0, unsigned& r1, unsigned& r2, unsigned& r3,
                                        unsigned addr) {
    asm volatile("ldmatrix.sync.aligned.m8n8.x4.shared.b16 {%0,%1,%2,%3}, [%4];"
                 : "=r"(r0), "=r"(r1), "=r"(r2), "=r"(r3) : "r"(addr));
}
__device__ __forceinline__ void ldsm_x2t(unsigned& r0, unsigned& r1, unsigned addr) {
    asm volatile("ldmatrix.sync.aligned.m8n8.x2.trans.shared.b16 {%0,%1}, [%2];"
                 : "=r"(r0), "=r"(r1) : "r"(addr));
}
__device__ __forceinline__ void mma_bf16(float* d, const unsigned* a, const unsigned* b) {
    asm volatile(
        "mma.sync.aligned.m16n8k16.row.col.f32.bf16.bf16.f32 "
        "{%0,%1,%2,%3}, {%4,%5,%6,%7}, {%8,%9}, {%0,%1,%2,%3};"
        : "+f"(d[0]), "+f"(d[1]), "+f"(d[2]), "+f"(d[3])
        : "r"(a[0]), "r"(a[1]), "r"(a[2]), "r"(a[3]), "r"(b[0]), "r"(b[1]));
}

// ---------------- tiny helpers ----------------------------------------------
__global__ void zero_deg_kernel() {
    int i = blockIdx.x * blockDim.x + threadIdx.x;
    int stride = gridDim.x * blockDim.x;
    for (; i < N_NODES; i += stride) g_deg[i] = 0;
}

__global__ void count_deg_kernel(const int* __restrict__ col, int E) {
    int i = blockIdx.x * blockDim.x + threadIdx.x;
    int stride = gridDim.x * blockDim.x;
    for (; i < E; i += stride) atomicAdd(&g_deg[col[i]], 1);
}

__global__ void __launch_bounds__(256) scan_a_kernel() {
    int b = blockIdx.x;
    int tid = threadIdx.x;
    int base = b * SCAN_TILE + tid * 4;
    int s = 0;
#pragma unroll
    for (int j = 0; j < 4; j++) {
        int idx = base + j;
        if (idx < N_NODES) s += g_deg[idx];
    }
    for (int o = 16; o > 0; o >>= 1) s += __shfl_down_sync(0xffffffffu, s, o);
    __shared__ int wsum[8];
    int lane = tid & 31, warp = tid >> 5;
    if (lane == 0) wsum[warp] = s;
    __syncthreads();
    if (tid == 0) {
        int t = 0;
        for (int w = 0; w < 8; w++) t += wsum[w];
        g_bsums[b] = t;
    }
}

__global__ void __launch_bounds__(128) scan_b_kernel() {
    int tid = threadIdx.x;
    int v = (tid < NB_SCAN) ? g_bsums[tid] : 0;
    int lane = tid & 31, w = tid >> 5;
    int incl = v;
    for (int o = 1; o < 32; o <<= 1) {
        int t = __shfl_up_sync(0xffffffffu, incl, o);
        if (lane >= o) incl += t;
    }
    __shared__ int ws[4];
    if (lane == 31) ws[w] = incl;
    __syncthreads();
    int woff = 0;
    for (int i = 0; i < w; i++) woff += ws[i];
    int excl = woff + incl - v;
    if (tid < NB_SCAN) g_boffs[tid] = excl;
    if (tid == NB_SCAN - 1) g_rowptr[N_NODES] = excl + v;
}

__global__ void __launch_bounds__(256) scan_c_kernel() {
    int b = blockIdx.x;
    int tid = threadIdx.x;
    int lane = tid & 31, warp = tid >> 5;
    int base = b * SCAN_TILE + tid * 4;
    int d[4];
#pragma unroll
    for (int j = 0; j < 4; j++) {
        int idx = base + j;
        d[j] = (idx < N_NODES) ? g_deg[idx] : 0;
    }
    int tsum = d[0] + d[1] + d[2] + d[3];
    int incl = tsum;
    for (int o = 1; o < 32; o <<= 1) {
        int v = __shfl_up_sync(0xffffffffu, incl, o);
        if (lane >= o) incl += v;
    }
    int excl = incl - tsum;
    __shared__ int wsum[8];
    if (lane == 31) wsum[warp] = incl;
    __syncthreads();
    int woff = 0;
    for (int w = 0; w < warp; w++) woff += wsum[w];
    int off = g_boffs[b] + woff + excl;
#pragma unroll
    for (int j = 0; j < 4; j++) {
        int idx = base + j;
        if (idx < N_NODES) {
            g_rowptr[idx] = off;
            g_cursor[idx] = off;
            g_dinv[idx]   = (d[j] > 0) ? rsqrtf((float)d[j]) : 0.0f;
            off += d[j];
        }
    }
}

__global__ void fill_csr_kernel(const int* __restrict__ row,
                                const int* __restrict__ col, int E) {
    int i = blockIdx.x * blockDim.x + threadIdx.x;
    int stride = gridDim.x * blockDim.x;
    for (; i < E; i += stride) {
        int c = col[i];
        int p = atomicAdd(&g_cursor[c], 1);
        g_csr[p] = row[i];
    }
}

// ---------------- weight image prep ------------------------------------------
// B'[k][n] padded [KTOT][B_STRIDE]: rows k<64 = hi(W[k]), 64..127 = lo(W[k-64]),
// 128..191 = hi(W[k-128]).  cols n<64 -> Wi, 64..127 -> Wr, >=128 -> 0 pad.
__global__ void __launch_bounds__(256) wprep_kernel(
    const float* __restrict__ w1i, const float* __restrict__ w1r,
    const float* __restrict__ w2i, const float* __restrict__ w2r)
{
    int idx = blockIdx.x * blockDim.x + threadIdx.x;
    if (idx >= 2 * KTOT * B_STRIDE) return;
    int layer = idx / (KTOT * B_STRIDE);
    int rem = idx % (KTOT * B_STRIDE);
    int k = rem / B_STRIDE;
    int n = rem % B_STRIDE;
    __nv_bfloat16 val = __float2bfloat16(0.f);
    if (n < N2) {
        int seg = k / 64, kk = k % 64;
        const float* W = (n < 64) ? (layer ? w2i : w1i) : (layer ? w2r : w1r);
        float w = W[kk * 64 + (n & 63)];
        __nv_bfloat16 hi = __float2bfloat16(w);
        val = (seg == 1) ? __float2bfloat16(w - __bfloat162float(hi)) : hi;
    }
    g_wb[layer][rem] = *reinterpret_cast<unsigned short*>(&val);
}

// ---------------- mma.sync dual GEMM -----------------------------------------
// D[128, 128] = A'[128, 192] @ B'[192, 128]; cols 0..63 -> T = dinv .* (X@Wi),
// cols 64..127 -> R = X@Wr.  256 threads = 8 warps (4 M-groups x 2 N-groups).
__global__ void __launch_bounds__(256) gemm_tc_kernel(
    const float* __restrict__ Xext, int use_ext, int layer, int n)
{
    extern __shared__ char dsm[];
    __nv_bfloat16* sA = (__nv_bfloat16*)dsm;            // [128][A_STRIDE]
    __nv_bfloat16* sB = (__nv_bfloat16*)(dsm + A_BYTES); // [192][B_STRIDE]

    int tid = threadIdx.x;
    int wid = tid >> 5, lane = tid & 31;
    int row0 = blockIdx.x * TILE_M;
    const float* X = use_ext ? Xext : (const float*)g_h1;

    // --- stage B' image (52KB from L2) ---
    {
        const uint4* src = (const uint4*)g_wb[layer];
        uint4* dst = (uint4*)sB;
        for (int i = tid; i < B_BYTES / 16; i += 256) dst[i] = src[i];
    }

    // --- convert A rows: fp32 -> (hi, hi, lo) bf16 segments ---
    {
        int r = tid >> 1;                   // 0..127
        int kh = (tid & 1) * 32;            // k half
        int grow = row0 + r;
        const float4* x4 = (const float4*)X;
        unsigned* arow = (unsigned*)(sA + r * A_STRIDE);
#pragma unroll
        for (int q = 0; q < 8; q++) {
            float4 v = make_float4(0.f, 0.f, 0.f, 0.f);
            if (grow < n) v = x4[(size_t)grow * 16 + (kh >> 2) + q];
            int k0 = kh + q * 4;
#pragma unroll
            for (int h = 0; h < 2; h++) {
                float a = h ? v.z : v.x;
                float b = h ? v.w : v.y;
                __nv_bfloat16 ah = __float2bfloat16(a);
                __nv_bfloat16 bh = __float2bfloat16(b);
                __nv_bfloat162 ph; ph.x = ah; ph.y = bh;
                __nv_bfloat162 pl;
                pl.x = __float2bfloat16(a - __bfloat162float(ah));
                pl.y = __float2bfloat16(b - __bfloat162float(bh));
                unsigned uh = *reinterpret_cast<unsigned*>(&ph);
                unsigned ul = *reinterpret_cast<unsigned*>(&pl);
                int e = (k0 + h * 2) >> 1;          // unsigned-index within row
                arow[e]      = uh;                  // seg 0: Ah
                arow[e + 32] = uh;                  // seg 1: Ah
                arow[e + 64] = ul;                  // seg 2: Al
            }
        }
    }
    __syncthreads();

    // --- mainloop ---
    int mwarp = (wid & 3) * 32;     // M base of this warp
    int nwarp = (wid >> 2);         // 0 -> T cols, 1 -> R cols
    int nbase = nwarp * 64;

    unsigned aAbase, aBbase;
    {
        unsigned sAu = smem_u32(sA);
        unsigned sBu = smem_u32(sB);
        // A: lane -> row (mwarp + (lane&15)), k-half (lane>>4)*8
        aAbase = sAu + (unsigned)((mwarp + (lane & 15)) * A_STRIDE * 2 + (lane >> 4) * 16);
        // B: lane -> k row (lane&15), col nbase
        aBbase = sBu + (unsigned)((lane & 15) * B_STRIDE * 2 + nbase * 2);
    }

    float acc[2][8][4];
#pragma unroll
    for (int t = 0; t < 2; t++)
#pragma unroll
        for (int j = 0; j < 8; j++)
#pragma unroll
            for (int c = 0; c < 4; c++) acc[t][j][c] = 0.f;

#pragma unroll
    for (int ks = 0; ks < KSTEPS; ks++) {
        unsigned a[2][4];
#pragma unroll
        for (int t = 0; t < 2; t++)
            ldsm_x4(a[t][0], a[t][1], a[t][2], a[t][3],
                    aAbase + (unsigned)(t * 16 * A_STRIDE * 2 + ks * 32));
        unsigned b[8][2];
#pragma unroll
        for (int j = 0; j < 8; j++)
            ldsm_x2t(b[j][0], b[j][1],
                     aBbase + (unsigned)(ks * 16 * B_STRIDE * 2 + j * 16));
#pragma unroll
        for (int t = 0; t < 2; t++)
#pragma unroll
            for (int j = 0; j < 8; j++)
                mma_bf16(acc[t][j], a[t], b[j]);
    }

    // --- epilogue: write T (scaled by dinv) and R ---
#pragma unroll
    for (int t = 0; t < 2; t++) {
        int r0 = row0 + mwarp + t * 16 + (lane >> 2);
        int r1 = r0 + 8;
        float dv0 = 1.f, dv1 = 1.f;
        if (nwarp == 0) {
            dv0 = (r0 < n) ? g_dinv[r0] : 0.f;
            dv1 = (r1 < n) ? g_dinv[r1] : 0.f;
        }
        float* dst = (nwarp == 0) ? g_t : g_r;
#pragma unroll
        for (int j = 0; j < 8; j++) {
            int c = j * 8 + (lane & 3) * 2;
            if (r0 < n) {
                float2 o = make_float2(acc[t][j][0] * dv0, acc[t][j][1] * dv0);
                *(float2*)(dst + (size_t)r0 * 64 + c) = o;
            }
            if (r1 < n) {
                float2 o = make_float2(acc[t][j][2] * dv1, acc[t][j][3] * dv1);
                *(float2*)(dst + (size_t)r1 * 64 + c) = o;
            }
        }
    }
}

// ---------------- propagate + root + bias + relu ----------------------------
__global__ void __launch_bounds__(256) prop_combine_kernel(
    const float* __restrict__ bias, int layer)
{
    float* H = layer == 0 ? g_h1 : g_h2;

    int warp = (blockIdx.x * blockDim.x + threadIdx.x) >> 5;
    int lane = threadIdx.x & 31;
    if (warp >= N_NODES) return;
    int node = warp;

    int s = g_rowptr[node];
    int e = g_rowptr[node + 1];

    const float2* T2 = (const float2*)g_t;
    float2 acc0 = make_float2(0.f, 0.f);
    float2 acc1 = make_float2(0.f, 0.f);

    int i = s;
    for (; i + 1 < e; i += 2) {
        int s0 = __ldg(&g_csr[i]);
        int s1 = __ldg(&g_csr[i + 1]);
        float2 v0 = T2[(size_t)s0 * 32 + lane];
        float2 v1 = T2[(size_t)s1 * 32 + lane];
        acc0.x += v0.x; acc0.y += v0.y;
        acc1.x += v1.x; acc1.y += v1.y;
    }
    if (i < e) {
        int s0 = __ldg(&g_csr[i]);
        float2 v0 = T2[(size_t)s0 * 32 + lane];
        acc0.x += v0.x; acc0.y += v0.y;
    }
    acc0.x += acc1.x; acc0.y += acc1.y;

    float dv = g_dinv[node];
    float2 r = ((const float2*)g_r)[(size_t)node * 32 + lane];
    float bx = bias[2 * lane], by = bias[2 * lane + 1];
    float hx = fmaf(dv, acc0.x, r.x + bx);
    float hy = fmaf(dv, acc0.y, r.y + by);
    hx = hx > 0.f ? hx : 0.f;
    hy = hy > 0.f ? hy : 0.f;
    ((float2*)H)[(size_t)node * 32 + lane] = make_float2(hx, hy);
}

// ---------------- global mean pool (sorted batch) + final FC ----------------
__device__ __forceinline__ int lbound_i(const int* a, int n, int key) {
    int lo = 0, hi = n;
    while (lo < hi) {
        int mid = (lo + hi) >> 1;
        if (a[mid] < key) lo = mid + 1; else hi = mid;
    }
    return lo;
}

__global__ void __launch_bounds__(256) pool_fc_kernel(
    const int* __restrict__ batch,
    const float* __restrict__ fcw, const float* __restrict__ fcb,
    float* __restrict__ out)
{
    const float* H = g_h2;
    int g = blockIdx.x;
    int tid = threadIdx.x;
    __shared__ int bounds[2];
    if (tid == 0) bounds[0] = lbound_i(batch, N_NODES, g);
    if (tid == 1) bounds[1] = lbound_i(batch, N_NODES, g + 1);
    __syncthreads();
    int lo = bounds[0], hi = bounds[1];

    int f   = tid & 63;
    int grp = tid >> 6;
    float acc = 0.f;
    for (int nidx = lo + grp; nidx < hi; nidx += 4)
        acc += H[(size_t)nidx * 64 + f];

    __shared__ float part[4][64];
    part[grp][f] = acc;
    __syncthreads();

    __shared__ float pooled[64];
    if (tid < 64) {
        float sfull = part[0][tid] + part[1][tid] + part[2][tid] + part[3][tid];
        int cnt = hi - lo;
        pooled[tid] = sfull / (float)(cnt > 0 ? cnt : 1);
    }
    __syncthreads();

    if (tid < OUT_DIM) {
        float o = fcb[tid];
#pragma unroll 8
        for (int k = 0; k < 64; k++) o = fmaf(pooled[k], fcw[k * OUT_DIM + tid], o);
        out[g * OUT_DIM + tid] = o;
    }
}

// ---------------- launcher ---------------------------------------------------
extern "C" void kernel_launch(void* const* d_in, const int* in_sizes, int n_in,
                              void* d_out, int out_size)
{
    const float* x     = (const float*)d_in[0];
    const int*   ei    = (const int*)d_in[1];     // [2, E] int32
    const int*   batch = (const int*)d_in[2];
    const float* w1i   = (const float*)d_in[3];
    const float* w1r   = (const float*)d_in[4];
    const float* b1    = (const float*)d_in[5];
    const float* w2i   = (const float*)d_in[6];
    const float* w2r   = (const float*)d_in[7];
    const float* b2    = (const float*)d_in[8];
    const float* fcw   = (const float*)d_in[9];
    const float* fcb   = (const float*)d_in[10];
    float*       out   = (float*)d_out;

    const int E = in_sizes[1] / 2;
    const int* row = ei;
    const int* col = ei + E;

    cudaFuncSetAttribute(gemm_tc_kernel,
                         cudaFuncAttributeMaxDynamicSharedMemorySize, GEMM_SMEM);

    // weight images (tiny)
    wprep_kernel<<<(2 * KTOT * B_STRIDE + 255) / 256, 256>>>(w1i, w1r, w2i, w2r);

    // CSR build
    zero_deg_kernel<<<196, 512>>>();
    count_deg_kernel<<<(E + 511) / 512, 512>>>(col, E);
    scan_a_kernel<<<NB_SCAN, 256>>>();
    scan_b_kernel<<<1, 128>>>();
    scan_c_kernel<<<NB_SCAN, 256>>>();
    fill_csr_kernel<<<(E + 511) / 512, 512>>>(row, col, E);

    // layer 1
    gemm_tc_kernel<<<GEMM_TILES, 256, GEMM_SMEM>>>(x, 1, 0, N_NODES);
    prop_combine_kernel<<<(N_NODES * 32 + 255) / 256, 256>>>(b1, 0);
    // layer 2
    gemm_tc_kernel<<<GEMM_TILES, 256, GEMM_SMEM>>>(nullptr, 0, 1, N_NODES);
    prop_combine_kernel<<<(N_NODES * 32 + 255) / 256, 256>>>(b2, 1);
    // pool + fc
    pool_fc_kernel<<<NUM_GRAPHS, 256>>>(batch, fcw, fcb, out);
}

// round 5
// speedup vs baseline: 1.2030x; 1.1134x over previous
#include <cuda_runtime.h>
#include <cuda_bf16.h>
#include <cuda_fp16.h>
#include <math.h>

// Problem constants (fixed by the dataset)
#define N_NODES   100000
#define E_EDGES   1600000
#define HDIM      64
#define OUT_DIM   32
#define NUM_GRAPHS 64

#define SCAN_TILE 1024
#define NB_SCAN   ((N_NODES + SCAN_TILE - 1) / SCAN_TILE)   // 98

// tensor GEMM geometry (mma.sync path)
#define TILE_M    128
#define KTOT      192            // [Ah|Ah|Al] x [Bh;Bl;Bh]
#define N2        128            // Wi|Wr side by side
#define KSTEPS    (KTOT / 16)    // 12
#define A_STRIDE  200            // bf16 elems per A row (192 + 8 pad)
#define B_STRIDE  136            // bf16 elems per B row (128 + 8 pad)
#define A_BYTES   (TILE_M * A_STRIDE * 2)     // 51200
#define B_BYTES   (KTOT * B_STRIDE * 2)       // 52224
#define GEMM_SMEM (A_BYTES + B_BYTES)         // 103424
#define GEMM_TILES ((N_NODES + TILE_M - 1) / TILE_M)   // 782

// ---------------- scratch (static device globals; no allocation) ------------
__device__ int   g_deg[N_NODES];
__device__ int   g_rowptr[N_NODES + 1];
__device__ int   g_bsums[NB_SCAN];
__device__ int   g_boffs[NB_SCAN];
__device__ int   g_csr[E_EDGES];
__device__ int   g_perm[E_EDGES];
__device__ __align__(16) float  g_dinv[N_NODES];
__device__ __align__(16) __half g_t [N_NODES * HDIM];    // fp16 propagate source
__device__ __align__(16) float  g_r [N_NODES * HDIM];
__device__ __align__(16) float  g_h1[N_NODES * HDIM];
__device__ __align__(16) float  g_h2[N_NODES * HDIM];
__device__ __align__(16) unsigned short g_wb[2][KTOT * B_STRIDE];  // padded B images

// ---------------- PTX helpers ------------------------------------------------
__device__ __forceinline__ unsigned smem_u32(const void* p) {
    unsigned a;
    asm("{ .reg .u64 t; cvta.to.shared.u64 t, %1; cvt.u32.u64 %0, t; }" : "=r"(a) : "l"(p));
    return a;
}
__device__ __forceinline__ void ldsm_x4(unsigned& r0, unsigned& r1, unsigned& r2, unsigned& r3,
                                        unsigned addr) {
    asm volatile("ldmatrix.sync.aligned.m8n8.x4.shared.b16 {%0,%1,%2,%3}, [%4];"
                 : "=r"(r0), "=r"(r1), "=r"(r2), "=r"(r3) : "r"(addr));
}
__device__ __forceinline__ void ldsm_x2t(unsigned& r0, unsigned& r1, unsigned addr) {
    asm volatile("ldmatrix.sync.aligned.m8n8.x2.trans.shared.b16 {%0,%1}, [%2];"
                 : "=r"(r0), "=r"(r1) : "r"(addr));
}
__device__ __forceinline__ void mma_bf16(float* d, const unsigned* a, const unsigned* b) {
    asm volatile(
        "mma.sync.aligned.m16n8k16.row.col.f32.bf16.bf16.f32 "
        "{%0,%1,%2,%3}, {%4,%5,%6,%7}, {%8,%9}, {%0,%1,%2,%3};"
        : "+f"(d[0]), "+f"(d[1]), "+f"(d[2]), "+f"(d[3])
        : "r"(a[0]), "r"(a[1]), "r"(a[2]), "r"(a[3]), "r"(b[0]), "r"(b[1]));
}

// ---------------- CSR build ----------------------------------------------------
__global__ void count_deg_kernel(const int* __restrict__ col, int E) {
    int i = blockIdx.x * blockDim.x + threadIdx.x;
    int stride = gridDim.x * blockDim.x;
    for (; i < E; i += stride) {
        g_perm[i] = atomicAdd(&g_deg[col[i]], 1);
    }
}

__global__ void __launch_bounds__(256) scan_a_kernel() {
    int b = blockIdx.x;
    int tid = threadIdx.x;
    int base = b * SCAN_TILE + tid * 4;
    int s = 0;
#pragma unroll
    for (int j = 0; j < 4; j++) {
        int idx = base + j;
        if (idx < N_NODES) s += g_deg[idx];
    }
    for (int o = 16; o > 0; o >>= 1) s += __shfl_down_sync(0xffffffffu, s, o);
    __shared__ int wsum[8];
    int lane = tid & 31, warp = tid >> 5;
    if (lane == 0) wsum[warp] = s;
    __syncthreads();
    if (tid == 0) {
        int t = 0;
        for (int w = 0; w < 8; w++) t += wsum[w];
        g_bsums[b] = t;
    }
}

__global__ void __launch_bounds__(128) scan_b_kernel() {
    int tid = threadIdx.x;
    int v = (tid < NB_SCAN) ? g_bsums[tid] : 0;
    int lane = tid & 31, w = tid >> 5;
    int incl = v;
    for (int o = 1; o < 32; o <<= 1) {
        int t = __shfl_up_sync(0xffffffffu, incl, o);
        if (lane >= o) incl += t;
    }
    __shared__ int ws[4];
    if (lane == 31) ws[w] = incl;
    __syncthreads();
    int woff = 0;
    for (int i = 0; i < w; i++) woff += ws[i];
    int excl = woff + incl - v;
    if (tid < NB_SCAN) g_boffs[tid] = excl;
    if (tid == NB_SCAN - 1) g_rowptr[N_NODES] = excl + v;
}

__global__ void __launch_bounds__(256) scan_c_kernel() {
    int b = blockIdx.x;
    int tid = threadIdx.x;
    int lane = tid & 31, warp = tid >> 5;
    int base = b * SCAN_TILE + tid * 4;
    int d[4];
#pragma unroll
    for (int j = 0; j < 4; j++) {
        int idx = base + j;
        d[j] = (idx < N_NODES) ? g_deg[idx] : 0;
    }
    int tsum = d[0] + d[1] + d[2] + d[3];
    int incl = tsum;
    for (int o = 1; o < 32; o <<= 1) {
        int v = __shfl_up_sync(0xffffffffu, incl, o);
        if (lane >= o) incl += v;
    }
    int excl = incl - tsum;
    __shared__ int wsum[8];
    if (lane == 31) wsum[warp] = incl;
    __syncthreads();
    int woff = 0;
    for (int w = 0; w < warp; w++) woff += wsum[w];
    int off = g_boffs[b] + woff + excl;
#pragma unroll
    for (int j = 0; j < 4; j++) {
        int idx = base + j;
        if (idx < N_NODES) {
            g_rowptr[idx] = off;
            g_dinv[idx]   = (d[j] > 0) ? rsqrtf((float)d[j]) : 0.0f;
            off += d[j];
        }
    }
}

// atomic-free fill using precomputed slots
__global__ void fill_csr_kernel(const int* __restrict__ row,
                                const int* __restrict__ col, int E) {
    int i = blockIdx.x * blockDim.x + threadIdx.x;
    int stride = gridDim.x * blockDim.x;
    for (; i < E; i += stride) {
        g_csr[g_rowptr[col[i]] + g_perm[i]] = row[i];
    }
}

// ---------------- weight image prep ------------------------------------------
__global__ void __launch_bounds__(256) wprep_kernel(
    const float* __restrict__ w1i, const float* __restrict__ w1r,
    const float* __restrict__ w2i, const float* __restrict__ w2r)
{
    int idx = blockIdx.x * blockDim.x + threadIdx.x;
    if (idx >= 2 * KTOT * B_STRIDE) return;
    int layer = idx / (KTOT * B_STRIDE);
    int rem = idx % (KTOT * B_STRIDE);
    int k = rem / B_STRIDE;
    int n = rem % B_STRIDE;
    __nv_bfloat16 val = __float2bfloat16(0.f);
    if (n < N2) {
        int seg = k / 64, kk = k % 64;
        const float* W = (n < 64) ? (layer ? w2i : w1i) : (layer ? w2r : w1r);
        float w = W[kk * 64 + (n & 63)];
        __nv_bfloat16 hi = __float2bfloat16(w);
        val = (seg == 1) ? __float2bfloat16(w - __bfloat162float(hi)) : hi;
    }
    g_wb[layer][rem] = *reinterpret_cast<unsigned short*>(&val);
}

// ---------------- mma.sync dual GEMM -----------------------------------------
// D[128, 128]; cols 0..63 -> T = fp16(dinv .* (X@Wi)), cols 64..127 -> R = X@Wr
__global__ void __launch_bounds__(256) gemm_tc_kernel(
    const float* __restrict__ Xext, int use_ext, int layer, int n)
{
    extern __shared__ char dsm[];
    __nv_bfloat16* sA = (__nv_bfloat16*)dsm;             // [128][A_STRIDE]
    __nv_bfloat16* sB = (__nv_bfloat16*)(dsm + A_BYTES); // [192][B_STRIDE]

    int tid = threadIdx.x;
    int wid = tid >> 5, lane = tid & 31;
    int row0 = blockIdx.x * TILE_M;
    const float* X = use_ext ? Xext : (const float*)g_h1;

    // stage B' image
    {
        const uint4* src = (const uint4*)g_wb[layer];
        uint4* dst = (uint4*)sB;
        for (int i = tid; i < B_BYTES / 16; i += 256) dst[i] = src[i];
    }

    // convert A rows: fp32 -> (hi, hi, lo) bf16 segments
    {
        int r = tid >> 1;
        int kh = (tid & 1) * 32;
        int grow = row0 + r;
        const float4* x4 = (const float4*)X;
        unsigned* arow = (unsigned*)(sA + r * A_STRIDE);
#pragma unroll
        for (int q = 0; q < 8; q++) {
            float4 v = make_float4(0.f, 0.f, 0.f, 0.f);
            if (grow < n) v = x4[(size_t)grow * 16 + (kh >> 2) + q];
            int k0 = kh + q * 4;
#pragma unroll
            for (int h = 0; h < 2; h++) {
                float a = h ? v.z : v.x;
                float b = h ? v.w : v.y;
                __nv_bfloat16 ah = __float2bfloat16(a);
                __nv_bfloat16 bh = __float2bfloat16(b);
                __nv_bfloat162 ph; ph.x = ah; ph.y = bh;
                __nv_bfloat162 pl;
                pl.x = __float2bfloat16(a - __bfloat162float(ah));
                pl.y = __float2bfloat16(b - __bfloat162float(bh));
                unsigned uh = *reinterpret_cast<unsigned*>(&ph);
                unsigned ul = *reinterpret_cast<unsigned*>(&pl);
                int e = (k0 + h * 2) >> 1;
                arow[e]      = uh;
                arow[e + 32] = uh;
                arow[e + 64] = ul;
            }
        }
    }
    __syncthreads();

    int mwarp = (wid & 3) * 32;
    int nwarp = (wid >> 2);
    int nbase = nwarp * 64;

    unsigned aAbase, aBbase;
    {
        unsigned sAu = smem_u32(sA);
        unsigned sBu = smem_u32(sB);
        aAbase = sAu + (unsigned)((mwarp + (lane & 15)) * A_STRIDE * 2 + (lane >> 4) * 16);
        aBbase = sBu + (unsigned)((lane & 15) * B_STRIDE * 2 + nbase * 2);
    }

    float acc[2][8][4];
#pragma unroll
    for (int t = 0; t < 2; t++)
#pragma unroll
        for (int j = 0; j < 8; j++)
#pragma unroll
            for (int c = 0; c < 4; c++) acc[t][j][c] = 0.f;

#pragma unroll
    for (int ks = 0; ks < KSTEPS; ks++) {
        unsigned a[2][4];
#pragma unroll
        for (int t = 0; t < 2; t++)
            ldsm_x4(a[t][0], a[t][1], a[t][2], a[t][3],
                    aAbase + (unsigned)(t * 16 * A_STRIDE * 2 + ks * 32));
        unsigned b[8][2];
#pragma unroll
        for (int j = 0; j < 8; j++)
            ldsm_x2t(b[j][0], b[j][1],
                     aBbase + (unsigned)(ks * 16 * B_STRIDE * 2 + j * 16));
#pragma unroll
        for (int t = 0; t < 2; t++)
#pragma unroll
            for (int j = 0; j < 8; j++)
                mma_bf16(acc[t][j], a[t], b[j]);
    }

    // epilogue
#pragma unroll
    for (int t = 0; t < 2; t++) {
        int r0 = row0 + mwarp + t * 16 + (lane >> 2);
        int r1 = r0 + 8;
        if (nwarp == 0) {
            float dv0 = (r0 < n) ? g_dinv[r0] : 0.f;
            float dv1 = (r1 < n) ? g_dinv[r1] : 0.f;
#pragma unroll
            for (int j = 0; j < 8; j++) {
                int c = j * 8 + (lane & 3) * 2;
                if (r0 < n)
                    *(__half2*)(g_t + (size_t)r0 * 64 + c) =
                        __floats2half2_rn(acc[t][j][0] * dv0, acc[t][j][1] * dv0);
                if (r1 < n)
                    *(__half2*)(g_t + (size_t)r1 * 64 + c) =
                        __floats2half2_rn(acc[t][j][2] * dv1, acc[t][j][3] * dv1);
            }
        } else {
#pragma unroll
            for (int j = 0; j < 8; j++) {
                int c = j * 8 + (lane & 3) * 2;
                if (r0 < n)
                    *(float2*)(g_r + (size_t)r0 * 64 + c) =
                        make_float2(acc[t][j][0], acc[t][j][1]);
                if (r1 < n)
                    *(float2*)(g_r + (size_t)r1 * 64 + c) =
                        make_float2(acc[t][j][2], acc[t][j][3]);
            }
        }
    }
}

// ---------------- propagate + root + bias + relu ----------------------------
// H[dst] = relu( dinv[dst] * sum_{e} T[src_e] + R[dst] + bias )   (T fp16)
__global__ void __launch_bounds__(256) prop_combine_kernel(
    const float* __restrict__ bias, int layer)
{
    float* H = layer == 0 ? g_h1 : g_h2;

    int warp = (blockIdx.x * blockDim.x + threadIdx.x) >> 5;
    int lane = threadIdx.x & 31;
    if (warp >= N_NODES) return;
    int node = warp;

    int s = g_rowptr[node];
    int e = g_rowptr[node + 1];

    const __half2* T2 = (const __half2*)g_t;
    float2 acc0 = make_float2(0.f, 0.f);
    float2 acc1 = make_float2(0.f, 0.f);

    int i = s;
    for (; i + 1 < e; i += 2) {
        int s0 = __ldg(&g_csr[i]);
        int s1 = __ldg(&g_csr[i + 1]);
        float2 v0 = __half22float2(T2[(size_t)s0 * 32 + lane]);
        float2 v1 = __half22float2(T2[(size_t)s1 * 32 + lane]);
        acc0.x += v0.x; acc0.y += v0.y;
        acc1.x += v1.x; acc1.y += v1.y;
    }
    if (i < e) {
        int s0 = __ldg(&g_csr[i]);
        float2 v0 = __half22float2(T2[(size_t)s0 * 32 + lane]);
        acc0.x += v0.x; acc0.y += v0.y;
    }
    acc0.x += acc1.x; acc0.y += acc1.y;

    float dv = g_dinv[node];
    float2 r = ((const float2*)g_r)[(size_t)node * 32 + lane];
    float bx = bias[2 * lane], by = bias[2 * lane + 1];
    float hx = fmaf(dv, acc0.x, r.x + bx);
    float hy = fmaf(dv, acc0.y, r.y + by);
    hx = hx > 0.f ? hx : 0.f;
    hy = hy > 0.f ? hy : 0.f;
    ((float2*)H)[(size_t)node * 32 + lane] = make_float2(hx, hy);
}

// ---------------- global mean pool (sorted batch) + final FC ----------------
__device__ __forceinline__ int lbound_i(const int* a, int n, int key) {
    int lo = 0, hi = n;
    while (lo < hi) {
        int mid = (lo + hi) >> 1;
        if (a[mid] < key) lo = mid + 1; else hi = mid;
    }
    return lo;
}

__global__ void __launch_bounds__(256) pool_fc_kernel(
    const int* __restrict__ batch,
    const float* __restrict__ fcw, const float* __restrict__ fcb,
    float* __restrict__ out)
{
    const float* H = g_h2;
    int g = blockIdx.x;
    int tid = threadIdx.x;
    __shared__ int bounds[2];
    if (tid == 0) bounds[0] = lbound_i(batch, N_NODES, g);
    if (tid == 1) bounds[1] = lbound_i(batch, N_NODES, g + 1);
    __syncthreads();
    int lo = bounds[0], hi = bounds[1];

    int f   = tid & 63;
    int grp = tid >> 6;
    float acc = 0.f;
    for (int nidx = lo + grp; nidx < hi; nidx += 4)
        acc += H[(size_t)nidx * 64 + f];

    __shared__ float part[4][64];
    part[grp][f] = acc;
    __syncthreads();

    __shared__ float pooled[64];
    if (tid < 64) {
        float sfull = part[0][tid] + part[1][tid] + part[2][tid] + part[3][tid];
        int cnt = hi - lo;
        pooled[tid] = sfull / (float)(cnt > 0 ? cnt : 1);
    }
    __syncthreads();

    if (tid < OUT_DIM) {
        float o = fcb[tid];
#pragma unroll 8
        for (int k = 0; k < 64; k++) o = fmaf(pooled[k], fcw[k * OUT_DIM + tid], o);
        out[g * OUT_DIM + tid] = o;
    }
}

// ---------------- launcher ---------------------------------------------------
extern "C" void kernel_launch(void* const* d_in, const int* in_sizes, int n_in,
                              void* d_out, int out_size)
{
    const float* x     = (const float*)d_in[0];
    const int*   ei    = (const int*)d_in[1];     // [2, E] int32
    const int*   batch = (const int*)d_in[2];
    const float* w1i   = (const float*)d_in[3];
    const float* w1r   = (const float*)d_in[4];
    const float* b1    = (const float*)d_in[5];
    const float* w2i   = (const float*)d_in[6];
    const float* w2r   = (const float*)d_in[7];
    const float* b2    = (const float*)d_in[8];
    const float* fcw   = (const float*)d_in[9];
    const float* fcb   = (const float*)d_in[10];
    float*       out   = (float*)d_out;

    const int E = in_sizes[1] / 2;
    const int* row = ei;
    const int* col = ei + E;

    cudaFuncSetAttribute(gemm_tc_kernel,
                         cudaFuncAttributeMaxDynamicSharedMemorySize, GEMM_SMEM);

    void* degp = nullptr;
    cudaGetSymbolAddress(&degp, g_deg);

    // weight images (tiny)
    wprep_kernel<<<(2 * KTOT * B_STRIDE + 255) / 256, 256>>>(w1i, w1r, w2i, w2r);

    // CSR build
    cudaMemsetAsync(degp, 0, N_NODES * sizeof(int));
    count_deg_kernel<<<(E + 511) / 512, 512>>>(col, E);
    scan_a_kernel<<<NB_SCAN, 256>>>();
    scan_b_kernel<<<1, 128>>>();
    scan_c_kernel<<<NB_SCAN, 256>>>();
    fill_csr_kernel<<<(E + 511) / 512, 512>>>(row, col, E);

    // layer 1
    gemm_tc_kernel<<<GEMM_TILES, 256, GEMM_SMEM>>>(x, 1, 0, N_NODES);
    prop_combine_kernel<<<(N_NODES * 32 + 255) / 256, 256>>>(b1, 0);
    // layer 2
    gemm_tc_kernel<<<GEMM_TILES, 256, GEMM_SMEM>>>(nullptr, 0, 1, N_NODES);
    prop_combine_kernel<<<(N_NODES * 32 + 255) / 256, 256>>>(b2, 1);
    // pool + fc
    pool_fc_kernel<<<NUM_GRAPHS, 256>>>(batch, fcw, fcb, out);
}

// round 6
// speedup vs baseline: 1.2532x; 1.0417x over previous
#include <cuda_runtime.h>
#include <cuda_bf16.h>
#include <cuda_fp16.h>
#include <math.h>

// Problem constants (fixed by the dataset)
#define N_NODES   100000
#define E_EDGES   1600000
#define HDIM      64
#define OUT_DIM   32
#define NUM_GRAPHS 64

#define SCAN_TILE 1024
#define NB_SCAN   ((N_NODES + SCAN_TILE - 1) / SCAN_TILE)   // 98

// tensor GEMM geometry (mma.sync path)
#define TILE_M    128
#define KTOT      192            // [Ah|Ah|Al] x [Bh;Bl;Bh]
#define N2        128            // Wi|Wr side by side
#define KSTEPS    (KTOT / 16)    // 12
#define A_STRIDE  200            // bf16 elems per A row (192 + 8 pad)
#define B_STRIDE  136            // bf16 elems per B row (128 + 8 pad)
#define A_BYTES   (TILE_M * A_STRIDE * 2)     // 51200
#define B_BYTES   (KTOT * B_STRIDE * 2)       // 52224
#define GEMM_SMEM (A_BYTES + B_BYTES)         // 103424
#define GEMM_TILES ((N_NODES + TILE_M - 1) / TILE_M)   // 782

// ---------------- scratch (static device globals; no allocation) ------------
__device__ int   g_deg[N_NODES];
__device__ int   g_rowptr[N_NODES + 1];
__device__ int   g_bsums[NB_SCAN];
__device__ int   g_csr[E_EDGES];
__device__ int   g_perm[E_EDGES];
__device__ __align__(16) float  g_dinv[N_NODES];
__device__ __align__(16) __half g_t [N_NODES * HDIM];    // fp16 propagate source
__device__ __align__(16) float  g_r [N_NODES * HDIM];
__device__ __align__(16) float  g_h1[N_NODES * HDIM];
__device__ __align__(16) float  g_pool[NUM_GRAPHS * HDIM];
__device__ __align__(16) unsigned short g_wb[2][KTOT * B_STRIDE];  // padded B images

// ---------------- PTX helpers ------------------------------------------------
__device__ __forceinline__ unsigned smem_u32(const void* p) {
    unsigned a;
    asm("{ .reg .u64 t; cvta.to.shared.u64 t, %1; cvt.u32.u64 %0, t; }" : "=r"(a) : "l"(p));
    return a;
}
__device__ __forceinline__ void ldsm_x4(unsigned& r0, unsigned& r1, unsigned& r2, unsigned& r3,
                                        unsigned addr) {
    asm volatile("ldmatrix.sync.aligned.m8n8.x4.shared.b16 {%0,%1,%2,%3}, [%4];"
                 : "=r"(r0), "=r"(r1), "=r"(r2), "=r"(r3) : "r"(addr));
}
__device__ __forceinline__ void ldsm_x2t(unsigned& r0, unsigned& r1, unsigned addr) {
    asm volatile("ldmatrix.sync.aligned.m8n8.x2.trans.shared.b16 {%0,%1}, [%2];"
                 : "=r"(r0), "=r"(r1) : "r"(addr));
}
__device__ __forceinline__ void mma_bf16(float* d, const unsigned* a, const unsigned* b) {
    asm volatile(
        "mma.sync.aligned.m16n8k16.row.col.f32.bf16.bf16.f32 "
        "{%0,%1,%2,%3}, {%4,%5,%6,%7}, {%8,%9}, {%0,%1,%2,%3};"
        : "+f"(d[0]), "+f"(d[1]), "+f"(d[2]), "+f"(d[3])
        : "r"(a[0]), "r"(a[1]), "r"(a[2]), "r"(a[3]), "r"(b[0]), "r"(b[1]));
}

// ---------------- CSR build ----------------------------------------------------
__global__ void count_deg_kernel(const int* __restrict__ col, int E) {
    int i = blockIdx.x * blockDim.x + threadIdx.x;
    int stride = gridDim.x * blockDim.x;
    for (; i < E; i += stride) {
        g_perm[i] = atomicAdd(&g_deg[col[i]], 1);
    }
}

__global__ void __launch_bounds__(256) scan_a_kernel() {
    int b = blockIdx.x;
    int tid = threadIdx.x;
    int base = b * SCAN_TILE + tid * 4;
    int s = 0;
#pragma unroll
    for (int j = 0; j < 4; j++) {
        int idx = base + j;
        if (idx < N_NODES) s += g_deg[idx];
    }
    for (int o = 16; o > 0; o >>= 1) s += __shfl_down_sync(0xffffffffu, s, o);
    __shared__ int wsum[8];
    int lane = tid & 31, warp = tid >> 5;
    if (lane == 0) wsum[warp] = s;
    __syncthreads();
    if (tid == 0) {
        int t = 0;
        for (int w = 0; w < 8; w++) t += wsum[w];
        g_bsums[b] = t;
    }
}

// fused: per-block offset from g_bsums + intra-block scan + dinv
__global__ void __launch_bounds__(256) scan_c_kernel() {
    int b = blockIdx.x;
    int tid = threadIdx.x;
    int lane = tid & 31, warp = tid >> 5;

    // block offset: reduce g_bsums[0..b)
    __shared__ int s_boff;
    {
        int v = (tid < b) ? g_bsums[tid] : 0;   // NB_SCAN=98 < 256
        for (int o = 16; o > 0; o >>= 1) v += __shfl_down_sync(0xffffffffu, v, o);
        __shared__ int ws[8];
        if (lane == 0) ws[warp] = v;
        __syncthreads();
        if (tid == 0) {
            int t = 0;
            for (int w = 0; w < 8; w++) t += ws[w];
            s_boff = t;
        }
        __syncthreads();
    }

    int base = b * SCAN_TILE + tid * 4;
    int d[4];
#pragma unroll
    for (int j = 0; j < 4; j++) {
        int idx = base + j;
        d[j] = (idx < N_NODES) ? g_deg[idx] : 0;
    }
    int tsum = d[0] + d[1] + d[2] + d[3];
    int incl = tsum;
    for (int o = 1; o < 32; o <<= 1) {
        int v = __shfl_up_sync(0xffffffffu, incl, o);
        if (lane >= o) incl += v;
    }
    int excl = incl - tsum;
    __shared__ int wsum[8];
    if (lane == 31) wsum[warp] = incl;
    __syncthreads();
    int woff = 0;
    for (int w = 0; w < warp; w++) woff += wsum[w];
    int off = s_boff + woff + excl;
#pragma unroll
    for (int j = 0; j < 4; j++) {
        int idx = base + j;
        if (idx < N_NODES) {
            g_rowptr[idx] = off;
            g_dinv[idx]   = (d[j] > 0) ? rsqrtf((float)d[j]) : 0.0f;
            off += d[j];
        }
    }
    if (b == NB_SCAN - 1 && tid == 255) g_rowptr[N_NODES] = off;
}

// atomic-free fill using precomputed slots
__global__ void fill_csr_kernel(const int* __restrict__ row,
                                const int* __restrict__ col, int E) {
    int i = blockIdx.x * blockDim.x + threadIdx.x;
    int stride = gridDim.x * blockDim.x;
    for (; i < E; i += stride) {
        g_csr[g_rowptr[col[i]] + g_perm[i]] = row[i];
    }
}

// ---------------- weight image prep ------------------------------------------
__global__ void __launch_bounds__(256) wprep_kernel(
    const float* __restrict__ w1i, const float* __restrict__ w1r,
    const float* __restrict__ w2i, const float* __restrict__ w2r)
{
    int idx = blockIdx.x * blockDim.x + threadIdx.x;
    if (idx >= 2 * KTOT * B_STRIDE) return;
    int layer = idx / (KTOT * B_STRIDE);
    int rem = idx % (KTOT * B_STRIDE);
    int k = rem / B_STRIDE;
    int n = rem % B_STRIDE;
    __nv_bfloat16 val = __float2bfloat16(0.f);
    if (n < N2) {
        int seg = k / 64, kk = k % 64;
        const float* W = (n < 64) ? (layer ? w2i : w1i) : (layer ? w2r : w1r);
        float w = W[kk * 64 + (n & 63)];
        __nv_bfloat16 hi = __float2bfloat16(w);
        val = (seg == 1) ? __float2bfloat16(w - __bfloat162float(hi)) : hi;
    }
    g_wb[layer][rem] = *reinterpret_cast<unsigned short*>(&val);
}

// ---------------- mma.sync dual GEMM -----------------------------------------
// D[128, 128]; cols 0..63 -> T = fp16(dinv .* (X@Wi)), cols 64..127 -> R = X@Wr
__global__ void __launch_bounds__(256) gemm_tc_kernel(
    const float* __restrict__ Xext, int use_ext, int layer, int n)
{
    extern __shared__ char dsm[];
    __nv_bfloat16* sA = (__nv_bfloat16*)dsm;             // [128][A_STRIDE]
    __nv_bfloat16* sB = (__nv_bfloat16*)(dsm + A_BYTES); // [192][B_STRIDE]

    int tid = threadIdx.x;
    int wid = tid >> 5, lane = tid & 31;
    int row0 = blockIdx.x * TILE_M;
    const float* X = use_ext ? Xext : (const float*)g_h1;

    // stage B' image
    {
        const uint4* src = (const uint4*)g_wb[layer];
        uint4* dst = (uint4*)sB;
        for (int i = tid; i < B_BYTES / 16; i += 256) dst[i] = src[i];
    }

    // convert A rows: fp32 -> (hi, hi, lo) bf16 segments
    {
        int r = tid >> 1;
        int kh = (tid & 1) * 32;
        int grow = row0 + r;
        const float4* x4 = (const float4*)X;
        unsigned* arow = (unsigned*)(sA + r * A_STRIDE);
#pragma unroll
        for (int q = 0; q < 8; q++) {
            float4 v = make_float4(0.f, 0.f, 0.f, 0.f);
            if (grow < n) v = x4[(size_t)grow * 16 + (kh >> 2) + q];
            int k0 = kh + q * 4;
#pragma unroll
            for (int h = 0; h < 2; h++) {
                float a = h ? v.z : v.x;
                float b = h ? v.w : v.y;
                __nv_bfloat16 ah = __float2bfloat16(a);
                __nv_bfloat16 bh = __float2bfloat16(b);
                __nv_bfloat162 ph; ph.x = ah; ph.y = bh;
                __nv_bfloat162 pl;
                pl.x = __float2bfloat16(a - __bfloat162float(ah));
                pl.y = __float2bfloat16(b - __bfloat162float(bh));
                unsigned uh = *reinterpret_cast<unsigned*>(&ph);
                unsigned ul = *reinterpret_cast<unsigned*>(&pl);
                int e = (k0 + h * 2) >> 1;
                arow[e]      = uh;
                arow[e + 32] = uh;
                arow[e + 64] = ul;
            }
        }
    }
    __syncthreads();

    int mwarp = (wid & 3) * 32;
    int nwarp = (wid >> 2);
    int nbase = nwarp * 64;

    unsigned aAbase, aBbase;
    {
        unsigned sAu = smem_u32(sA);
        unsigned sBu = smem_u32(sB);
        aAbase = sAu + (unsigned)((mwarp + (lane & 15)) * A_STRIDE * 2 + (lane >> 4) * 16);
        aBbase = sBu + (unsigned)((lane & 15) * B_STRIDE * 2 + nbase * 2);
    }

    float acc[2][8][4];
#pragma unroll
    for (int t = 0; t < 2; t++)
#pragma unroll
        for (int j = 0; j < 8; j++)
#pragma unroll
            for (int c = 0; c < 4; c++) acc[t][j][c] = 0.f;

#pragma unroll
    for (int ks = 0; ks < KSTEPS; ks++) {
        unsigned a[2][4];
#pragma unroll
        for (int t = 0; t < 2; t++)
            ldsm_x4(a[t][0], a[t][1], a[t][2], a[t][3],
                    aAbase + (unsigned)(t * 16 * A_STRIDE * 2 + ks * 32));
        unsigned b[8][2];
#pragma unroll
        for (int j = 0; j < 8; j++)
            ldsm_x2t(b[j][0], b[j][1],
                     aBbase + (unsigned)(ks * 16 * B_STRIDE * 2 + j * 16));
#pragma unroll
        for (int t = 0; t < 2; t++)
#pragma unroll
            for (int j = 0; j < 8; j++)
                mma_bf16(acc[t][j], a[t], b[j]);
    }

    // epilogue
#pragma unroll
    for (int t = 0; t < 2; t++) {
        int r0 = row0 + mwarp + t * 16 + (lane >> 2);
        int r1 = r0 + 8;
        if (nwarp == 0) {
            float dv0 = (r0 < n) ? g_dinv[r0] : 0.f;
            float dv1 = (r1 < n) ? g_dinv[r1] : 0.f;
#pragma unroll
            for (int j = 0; j < 8; j++) {
                int c = j * 8 + (lane & 3) * 2;
                if (r0 < n)
                    *(__half2*)(g_t + (size_t)r0 * 64 + c) =
                        __floats2half2_rn(acc[t][j][0] * dv0, acc[t][j][1] * dv0);
                if (r1 < n)
                    *(__half2*)(g_t + (size_t)r1 * 64 + c) =
                        __floats2half2_rn(acc[t][j][2] * dv1, acc[t][j][3] * dv1);
            }
        } else {
#pragma unroll
            for (int j = 0; j < 8; j++) {
                int c = j * 8 + (lane & 3) * 2;
                if (r0 < n)
                    *(float2*)(g_r + (size_t)r0 * 64 + c) =
                        make_float2(acc[t][j][0], acc[t][j][1]);
                if (r1 < n)
                    *(float2*)(g_r + (size_t)r1 * 64 + c) =
                        make_float2(acc[t][j][2], acc[t][j][3]);
            }
        }
    }
}

// ---------------- propagate + root + bias + relu (+ optional pool) ----------
// h[dst] = relu( dinv[dst] * sum_{e} T[src_e] + R[dst] + bias )
// layer 0: write g_h1.  layer 1: accumulate into g_pool (never materialize h2).
template <int LAYER>
__global__ void __launch_bounds__(256) prop_combine_kernel(
    const float* __restrict__ bias, const int* __restrict__ batch)
{
    __shared__ float pacc[64];
    int tid = threadIdx.x;
    if (LAYER == 1) {
        if (tid < 64) pacc[tid] = 0.f;
        __syncthreads();
    }

    int warp = (blockIdx.x * blockDim.x + tid) >> 5;
    int lane = tid & 31;
    int node = warp;

    if (node < N_NODES) {
        int s = g_rowptr[node];
        int e = g_rowptr[node + 1];

        const __half2* T2 = (const __half2*)g_t;
        float2 acc0 = make_float2(0.f, 0.f);
        float2 acc1 = make_float2(0.f, 0.f);
        float2 acc2 = make_float2(0.f, 0.f);
        float2 acc3 = make_float2(0.f, 0.f);

        int i = s;
        for (; i + 3 < e; i += 4) {
            int s0 = __ldg(&g_csr[i]);
            int s1 = __ldg(&g_csr[i + 1]);
            int s2 = __ldg(&g_csr[i + 2]);
            int s3 = __ldg(&g_csr[i + 3]);
            float2 v0 = __half22float2(T2[(size_t)s0 * 32 + lane]);
            float2 v1 = __half22float2(T2[(size_t)s1 * 32 + lane]);
            float2 v2 = __half22float2(T2[(size_t)s2 * 32 + lane]);
            float2 v3 = __half22float2(T2[(size_t)s3 * 32 + lane]);
            acc0.x += v0.x; acc0.y += v0.y;
            acc1.x += v1.x; acc1.y += v1.y;
            acc2.x += v2.x; acc2.y += v2.y;
            acc3.x += v3.x; acc3.y += v3.y;
        }
        for (; i < e; i++) {
            int s0 = __ldg(&g_csr[i]);
            float2 v0 = __half22float2(T2[(size_t)s0 * 32 + lane]);
            acc0.x += v0.x; acc0.y += v0.y;
        }
        acc0.x += acc1.x + acc2.x + acc3.x;
        acc0.y += acc1.y + acc2.y + acc3.y;

        float dv = g_dinv[node];
        float2 r = ((const float2*)g_r)[(size_t)node * 32 + lane];
        float bx = bias[2 * lane], by = bias[2 * lane + 1];
        float hx = fmaf(dv, acc0.x, r.x + bx);
        float hy = fmaf(dv, acc0.y, r.y + by);
        hx = hx > 0.f ? hx : 0.f;
        hy = hy > 0.f ? hy : 0.f;

        if (LAYER == 0) {
            ((float2*)g_h1)[(size_t)node * 32 + lane] = make_float2(hx, hy);
        } else {
            int gme = __ldg(&batch[node]);
            int g0  = __ldg(&batch[blockIdx.x * 8]);   // CTA's first node's graph
            if (gme == g0) {
                atomicAdd(&pacc[2 * lane], hx);
                atomicAdd(&pacc[2 * lane + 1], hy);
            } else {
                atomicAdd(&g_pool[gme * 64 + 2 * lane], hx);
                atomicAdd(&g_pool[gme * 64 + 2 * lane + 1], hy);
            }
        }
    }

    if (LAYER == 1) {
        __syncthreads();
        if (tid < 64) {
            int g0 = __ldg(&batch[blockIdx.x * 8 < N_NODES ? blockIdx.x * 8 : N_NODES - 1]);
            atomicAdd(&g_pool[g0 * 64 + tid], pacc[tid]);
        }
    }
}

// ---------------- final FC on pooled means -----------------------------------
__device__ __forceinline__ int lbound_i(const int* a, int n, int key) {
    int lo = 0, hi = n;
    while (lo < hi) {
        int mid = (lo + hi) >> 1;
        if (a[mid] < key) lo = mid + 1; else hi = mid;
    }
    return lo;
}

__global__ void __launch_bounds__(64) fc_kernel(
    const int* __restrict__ batch,
    const float* __restrict__ fcw, const float* __restrict__ fcb,
    float* __restrict__ out)
{
    int g = blockIdx.x;
    int tid = threadIdx.x;

    __shared__ float pooled[64];
    __shared__ int s_cnt;
    if (tid == 0) s_cnt = lbound_i(batch, N_NODES, g + 1) - lbound_i(batch, N_NODES, g);
    __syncthreads();
    float inv = 1.f / (float)(s_cnt > 0 ? s_cnt : 1);
    pooled[tid] = g_pool[g * 64 + tid] * inv;
    __syncthreads();

    if (tid < OUT_DIM) {
        float o = fcb[tid];
#pragma unroll 8
        for (int k = 0; k < 64; k++) o = fmaf(pooled[k], fcw[k * OUT_DIM + tid], o);
        out[g * OUT_DIM + tid] = o;
    }
}

// ---------------- launcher ---------------------------------------------------
extern "C" void kernel_launch(void* const* d_in, const int* in_sizes, int n_in,
                              void* d_out, int out_size)
{
    const float* x     = (const float*)d_in[0];
    const int*   ei    = (const int*)d_in[1];     // [2, E] int32
    const int*   batch = (const int*)d_in[2];
    const float* w1i   = (const float*)d_in[3];
    const float* w1r   = (const float*)d_in[4];
    const float* b1    = (const float*)d_in[5];
    const float* w2i   = (const float*)d_in[6];
    const float* w2r   = (const float*)d_in[7];
    const float* b2    = (const float*)d_in[8];
    const float* fcw   = (const float*)d_in[9];
    const float* fcb   = (const float*)d_in[10];
    float*       out   = (float*)d_out;

    const int E = in_sizes[1] / 2;
    const int* row = ei;
    const int* col = ei + E;

    cudaFuncSetAttribute(gemm_tc_kernel,
                         cudaFuncAttributeMaxDynamicSharedMemorySize, GEMM_SMEM);

    void* degp = nullptr;  void* poolp = nullptr;
    cudaGetSymbolAddress(&degp, g_deg);
    cudaGetSymbolAddress(&poolp, g_pool);

    // CSR build
    cudaMemsetAsync(degp, 0, N_NODES * sizeof(int));
    cudaMemsetAsync(poolp, 0, NUM_GRAPHS * HDIM * sizeof(float));
    count_deg_kernel<<<(E + 511) / 512, 512>>>(col, E);
    scan_a_kernel<<<NB_SCAN, 256>>>();
    scan_c_kernel<<<NB_SCAN, 256>>>();
    fill_csr_kernel<<<(E + 511) / 512, 512>>>(row, col, E);

    // weight images (tiny, independent of CSR)
    wprep_kernel<<<(2 * KTOT * B_STRIDE + 255) / 256, 256>>>(w1i, w1r, w2i, w2r);

    // layer 1
    gemm_tc_kernel<<<GEMM_TILES, 256, GEMM_SMEM>>>(x, 1, 0, N_NODES);
    prop_combine_kernel<0><<<(N_NODES * 32 + 255) / 256, 256>>>(b1, batch);
    // layer 2 (pool fused into propagate)
    gemm_tc_kernel<<<GEMM_TILES, 256, GEMM_SMEM>>>(nullptr, 0, 1, N_NODES);
    prop_combine_kernel<1><<<(N_NODES * 32 + 255) / 256, 256>>>(b2, batch);
    // final FC
    fc_kernel<<<NUM_GRAPHS, 64>>>(batch, fcw, fcb, out);
}